// round 15
// baseline (speedup 1.0000x reference)
#include <cuda_runtime.h>
#include <cuda_bf16.h>
#include <math.h>
#include <stdint.h>

// ---- problem constants ----
#define Bq   4
#define Tt   10
#define CINq 8
#define Hh   96
#define Ww   96
#define HW   9216
#define HID  64
#define Lq   13
#define C3   192
#define KW   832
#define FCH  32

// ---- scratch ----
__device__ float g_i2h[(size_t)Bq * Tt * C3 * HW];
__device__ float g_hA[(size_t)Bq * HID * HW];       // planar (fconv src)
__device__ float g_hB[(size_t)Bq * HID * HW];
__device__ float g_hTA[(size_t)Bq * HW * HID];      // channel-contig (gather src)
__device__ float g_hTB[(size_t)Bq * HW * HID];
__device__ float g_fp0[(size_t)Bq * FCH * HW];
__device__ float g_fp1[(size_t)Bq * FCH * HW];
__device__ float g_flows[(size_t)Bq * 2 * Lq * HW];
__device__ __nv_bfloat16 g_Bh16[(size_t)C3 * KW];
__device__ __nv_bfloat16 g_Bl16[(size_t)C3 * KW];

// ---- helpers ----
typedef unsigned long long u64;
__device__ __forceinline__ u64 pack2(float x, float y) {
    u64 r; asm("mov.b64 %0, {%1,%2};" : "=l"(r) : "f"(x), "f"(y)); return r;
}
__device__ __forceinline__ void unpack2(u64 v, float& x, float& y) {
    asm("mov.b64 {%0,%1}, %2;" : "=f"(x), "=f"(y) : "l"(v));
}
__device__ __forceinline__ void fma2(u64& d, u64 a, u64 b) {
    asm("fma.rn.f32x2 %0, %1, %2, %0;" : "+l"(d) : "l"(a), "l"(b));
}
__device__ __forceinline__ float tanh_fast(float x) {
    float t = __expf(-2.f * fabsf(x));
    float r = (1.f - t) / (1.f + t);
    return copysignf(r, x);
}
__device__ __forceinline__ float sigmoid_fast(float x) {
    return 1.f / (1.f + __expf(-x));
}
#define CP_ASYNC16(dst, src) \
    asm volatile("cp.async.cg.shared.global [%0], [%1], 16;" :: "r"(dst), "l"(src))
#define CP_COMMIT() asm volatile("cp.async.commit_group;")
#define CP_WAIT0()  asm volatile("cp.async.wait_group 0;")

// ---------------------------------------------------------------------------
__global__ void k_init_h(const float* __restrict__ state) {
    int i = blockIdx.x * 256 + threadIdx.x;
    if (i < Bq * HID * HW) {
        float v = state[i];
        g_hA[i] = v;
        int p = i % HW;
        int c = (i / HW) % HID;
        int b = i / (HW * HID);
        g_hTA[((size_t)b * HW + p) * HID + c] = v;
    }
}
__global__ void k_hlast(float* __restrict__ dst) {
    int i = blockIdx.x * 256 + threadIdx.x;
    if (i < Bq * HID * HW) dst[i] = g_hA[i];
}
__global__ void k_prep_b(const float* __restrict__ wrap_w) {
    int i = blockIdx.x * 256 + threadIdx.x;
    if (i < C3 * KW) {
        float v = wrap_w[i];
        __nv_bfloat16 h = __float2bfloat16(v);
        g_Bh16[i] = h;
        g_Bl16[i] = __float2bfloat16(v - __bfloat162float(h));
    }
}

// ---------------------------------------------------------------------------
// i2h: conv3x3 pad1. grid (6,6,240): z = n + 40*cog, cog selects 32 co.
__global__ __launch_bounds__(128)
void k_i2h(const float* __restrict__ x, const float* __restrict__ w,
           const float* __restrict__ bias) {
    __shared__ float s_in[CINq * 18 * 18];
    __shared__ __align__(16) float s_w[72 * 32];
    const int n   = blockIdx.z % 40;
    const int cob = (blockIdx.z / 40) * 32;
    const int y0 = blockIdx.y * 16, x0 = blockIdx.x * 16;
    const int tid = threadIdx.x;
    const int tx = tid & 15, ty = tid >> 4;

    const float* xin = x + (size_t)n * CINq * HW;
    for (int idx = tid; idx < CINq * 18 * 18; idx += 128) {
        int ci = idx / 324, r = (idx / 18) % 18, c = idx % 18;
        int gy = y0 - 1 + r, gx = x0 - 1 + c;
        float v = 0.f;
        if (gy >= 0 && gy < Hh && gx >= 0 && gx < Ww) v = xin[ci * HW + gy * Ww + gx];
        s_in[idx] = v;
    }
    for (int idx = tid; idx < 72 * 32; idx += 128) {
        int kk = idx >> 5, co = idx & 31;
        s_w[idx] = w[(cob + co) * 72 + kk];
    }
    __syncthreads();

    u64 accA[16], accB[16];
#pragma unroll
    for (int q = 0; q < 16; q++) {
        u64 v = pack2(bias[cob + 2 * q], bias[cob + 2 * q + 1]);
        accA[q] = v; accB[q] = v;
    }
    const u64* sw8 = (const u64*)s_w;
    for (int ci = 0; ci < CINq; ci++) {
#pragma unroll
        for (int ky = 0; ky < 3; ky++) {
            const float* r0 = &s_in[ci * 324 + (ty + ky) * 18 + tx];
            const float* r1 = &s_in[ci * 324 + (ty + 8 + ky) * 18 + tx];
#pragma unroll
            for (int kx = 0; kx < 3; kx++) {
                u64 a0 = pack2(r0[kx], r0[kx]);
                u64 a1 = pack2(r1[kx], r1[kx]);
                const u64* wp = sw8 + (ci * 9 + ky * 3 + kx) * 16;
#pragma unroll
                for (int h = 0; h < 4; h++) {
                    ulonglong2 wA = *(const ulonglong2*)(wp + h * 4);
                    ulonglong2 wB = *(const ulonglong2*)(wp + h * 4 + 2);
                    fma2(accA[h * 4 + 0], a0, wA.x); fma2(accB[h * 4 + 0], a1, wA.x);
                    fma2(accA[h * 4 + 1], a0, wA.y); fma2(accB[h * 4 + 1], a1, wA.y);
                    fma2(accA[h * 4 + 2], a0, wB.x); fma2(accB[h * 4 + 2], a1, wB.x);
                    fma2(accA[h * 4 + 3], a0, wB.y); fma2(accB[h * 4 + 3], a1, wB.y);
                }
            }
        }
    }
    float* outp = g_i2h + (size_t)n * C3 * HW + (size_t)cob * HW + (y0 + ty) * Ww + (x0 + tx);
#pragma unroll
    for (int q = 0; q < 16; q++) {
        float v0, v1, v2, v3;
        unpack2(accA[q], v0, v1);
        unpack2(accB[q], v2, v3);
        outp[(size_t)(2 * q) * HW] = v0;
        outp[(size_t)(2 * q + 1) * HW] = v1;
        outp[(size_t)(2 * q) * HW + 8 * Ww] = v2;
        outp[(size_t)(2 * q + 1) * HW + 8 * Ww] = v3;
    }
}

// ---------------------------------------------------------------------------
// fconv split by input chunks. grid (6,6,16): z = b + 4*grp + 8*half.
__global__ __launch_bounds__(128)
void k_fconv_half(const float* __restrict__ xall, int t, int swap,
                  const float* __restrict__ wi, const float* __restrict__ bi,
                  const float* __restrict__ wh, const float* __restrict__ bh) {
    __shared__ float s_in[8 * 400];
    __shared__ __align__(16) float s_w[200 * 16];
    const int b    = blockIdx.z & 3;
    const int grp  = (blockIdx.z >> 2) & 1;
    const int half = blockIdx.z >> 3;
    const int co0 = grp * 16;
    const int y0 = blockIdx.y * 16, x0 = blockIdx.x * 16;
    const int tid = threadIdx.x;
    const int tx = tid & 15, ty = tid >> 4;
    const float* hsrc = swap ? g_hB : g_hA;

    u64 accA[8], accB[8];
#pragma unroll
    for (int q = 0; q < 8; q++) {
        u64 v = half ? 0ull
                     : pack2(bi[co0 + 2 * q] + bh[co0 + 2 * q],
                             bi[co0 + 2 * q + 1] + bh[co0 + 2 * q + 1]);
        accA[q] = v; accB[q] = v;
    }

    const int c_lo = half ? 5 : 0;
    const int c_hi = half ? 9 : 5;
    for (int chunk = c_lo; chunk < c_hi; chunk++) {
        const float* src = (chunk == 0)
            ? xall + (size_t)(b * Tt + t) * CINq * HW
            : hsrc + (size_t)b * HID * HW + (size_t)(chunk - 1) * 8 * HW;
        __syncthreads();
        for (int idx = tid; idx < 8 * 400; idx += 128) {
            int ci = idx / 400, r = (idx / 20) % 20, c = idx % 20;
            int gy = y0 - 2 + r, gx = x0 - 2 + c;
            float v = 0.f;
            if (gy >= 0 && gy < Hh && gx >= 0 && gx < Ww) v = src[ci * HW + gy * Ww + gx];
            s_in[idx] = v;
        }
        if (chunk == 0) {
            for (int idx = tid; idx < 200 * 16; idx += 128) {
                int kk = idx >> 4, co = idx & 15;
                s_w[idx] = wi[(co0 + co) * 200 + kk];
            }
        } else {
            int cioff = (chunk - 1) * 8;
            for (int idx = tid; idx < 200 * 16; idx += 128) {
                int kk = idx >> 4, co = idx & 15;
                int ci = kk / 25, k25 = kk % 25;
                s_w[idx] = wh[((co0 + co) * 64 + cioff + ci) * 25 + k25];
            }
        }
        __syncthreads();
        const u64* sw8 = (const u64*)s_w;
        for (int ci = 0; ci < 8; ci++) {
#pragma unroll
            for (int ky = 0; ky < 5; ky++) {
                const float* r0 = &s_in[ci * 400 + (ty + ky) * 20 + tx];
                const float* r1 = &s_in[ci * 400 + (ty + 8 + ky) * 20 + tx];
#pragma unroll
                for (int kx = 0; kx < 5; kx++) {
                    u64 a0 = pack2(r0[kx], r0[kx]);
                    u64 a1 = pack2(r1[kx], r1[kx]);
                    const u64* wp = sw8 + (ci * 25 + ky * 5 + kx) * 8;
#pragma unroll
                    for (int h = 0; h < 2; h++) {
                        ulonglong2 wA = *(const ulonglong2*)(wp + h * 4);
                        ulonglong2 wB = *(const ulonglong2*)(wp + h * 4 + 2);
                        fma2(accA[h * 4 + 0], a0, wA.x); fma2(accB[h * 4 + 0], a1, wA.x);
                        fma2(accA[h * 4 + 1], a0, wA.y); fma2(accB[h * 4 + 1], a1, wA.y);
                        fma2(accA[h * 4 + 2], a0, wB.x); fma2(accB[h * 4 + 2], a1, wB.x);
                        fma2(accA[h * 4 + 3], a0, wB.y); fma2(accB[h * 4 + 3], a1, wB.y);
                    }
                }
            }
        }
    }
    float* base = half ? g_fp1 : g_fp0;
    float* outp = base + (size_t)b * FCH * HW + (size_t)co0 * HW + (y0 + ty) * Ww + (x0 + tx);
#pragma unroll
    for (int q = 0; q < 8; q++) {
        float v0, v1, v2, v3;
        unpack2(accA[q], v0, v1);
        unpack2(accB[q], v2, v3);
        outp[(size_t)(2 * q) * HW] = v0;
        outp[(size_t)(2 * q + 1) * HW] = v1;
        outp[(size_t)(2 * q) * HW + 8 * Ww] = v2;
        outp[(size_t)(2 * q + 1) * HW + 8 * Ww] = v3;
    }
}

// ---------------------------------------------------------------------------
// flows = conv5x5(tanh(fp0+fp1)). Combine fused into staging.
__global__ __launch_bounds__(128)
void k_flows(const float* __restrict__ w, const float* __restrict__ bias) {
    __shared__ float s_in[8 * 400];
    __shared__ __align__(16) float s_w[200 * 14];
    const int b   = blockIdx.z & 3;
    const int grp = blockIdx.z >> 2;
    const int co0 = grp * 13;
    const int y0 = blockIdx.y * 16, x0 = blockIdx.x * 16;
    const int tid = threadIdx.x;
    const int tx = tid & 15, ty = tid >> 4;

    u64 accA[7], accB[7];
#pragma unroll
    for (int q = 0; q < 7; q++) {
        float b0 = bias[co0 + 2 * q];
        float b1 = (2 * q + 1 < 13) ? bias[co0 + 2 * q + 1] : 0.f;
        u64 v = pack2(b0, b1);
        accA[q] = v; accB[q] = v;
    }

    for (int chunk = 0; chunk < 4; chunk++) {
        const float* s0 = g_fp0 + (size_t)b * FCH * HW + (size_t)chunk * 8 * HW;
        const float* s1 = g_fp1 + (size_t)b * FCH * HW + (size_t)chunk * 8 * HW;
        __syncthreads();
        for (int idx = tid; idx < 8 * 400; idx += 128) {
            int ci = idx / 400, r = (idx / 20) % 20, c = idx % 20;
            int gy = y0 - 2 + r, gx = x0 - 2 + c;
            float v = 0.f;
            if (gy >= 0 && gy < Hh && gx >= 0 && gx < Ww) {
                int off = ci * HW + gy * Ww + gx;
                v = tanh_fast(s0[off] + s1[off]);
            }
            s_in[idx] = v;
        }
        int cioff = chunk * 8;
        for (int idx = tid; idx < 200 * 14; idx += 128) {
            int kk = idx / 14, co = idx % 14;
            int ci = kk / 25, k25 = kk % 25;
            float v = 0.f;
            if (co < 13) v = w[((co0 + co) * 32 + cioff + ci) * 25 + k25];
            s_w[idx] = v;
        }
        __syncthreads();
        const u64* sw8 = (const u64*)s_w;
        for (int ci = 0; ci < 8; ci++) {
#pragma unroll
            for (int ky = 0; ky < 5; ky++) {
                const float* r0 = &s_in[ci * 400 + (ty + ky) * 20 + tx];
                const float* r1 = &s_in[ci * 400 + (ty + 8 + ky) * 20 + tx];
#pragma unroll
                for (int kx = 0; kx < 5; kx++) {
                    u64 a0 = pack2(r0[kx], r0[kx]);
                    u64 a1 = pack2(r1[kx], r1[kx]);
                    const u64* wp = sw8 + (ci * 25 + ky * 5 + kx) * 7;
#pragma unroll
                    for (int q = 0; q < 7; q++) {
                        u64 w2 = wp[q];
                        fma2(accA[q], a0, w2);
                        fma2(accB[q], a1, w2);
                    }
                }
            }
        }
    }
    float* outp = g_flows + (size_t)b * 2 * Lq * HW + (size_t)co0 * HW + (y0 + ty) * Ww + (x0 + tx);
#pragma unroll
    for (int q = 0; q < 7; q++) {
        float v0, v1, v2, v3;
        unpack2(accA[q], v0, v1);
        unpack2(accB[q], v2, v3);
        outp[(size_t)(2 * q) * HW] = v0;
        outp[(size_t)(2 * q) * HW + 8 * Ww] = v2;
        if (2 * q + 1 < 13) {
            outp[(size_t)(2 * q + 1) * HW] = v1;
            outp[(size_t)(2 * q + 1) * HW + 8 * Ww] = v3;
        }
    }
}

// ---------------------------------------------------------------------------
// h2h GEMM: bf16 m16n8k16, 2-term. Double-buffered, fused gather (float4 from
// channel-contiguous hT) + register gate epilogue.
#define AW 20
#define A_ST_W 2560
#define B_OFF_W 5120
#define B_ST_W 7680
#define B_LO_W 3840
#define G_SMEM_BYTES 81920

__device__ __forceinline__ void mma16(float d[4], const uint32_t a[4],
                                      uint32_t b0, uint32_t b1) {
    asm volatile(
        "mma.sync.aligned.m16n8k16.row.col.f32.bf16.bf16.f32 "
        "{%0,%1,%2,%3}, {%4,%5,%6,%7}, {%8,%9}, {%0,%1,%2,%3};"
        : "+f"(d[0]), "+f"(d[1]), "+f"(d[2]), "+f"(d[3])
        : "r"(a[0]), "r"(a[1]), "r"(a[2]), "r"(a[3]), "r"(b0), "r"(b1));
}

__global__ __launch_bounds__(256, 1)
void k_gemm_mma(const float* __restrict__ wrap_b, float* __restrict__ out,
                int t, int swap) {
    extern __shared__ __align__(16) float sm[];
    const uint32_t sm_sh = (uint32_t)__cvta_generic_to_shared(sm);

    const int tid = threadIdx.x;
    const int wid = tid >> 5, lane = tid & 31;
    const int g = lane >> 2, tg = lane & 3;
    const int b  = blockIdx.y;
    const int p0 = blockIdx.x * 128;
    const int wm = (wid >> 2) * 64;
    const int wn16 = (wid & 3) * 16;

    const float* h_r = swap ? g_hB : g_hA;
    float*       h_w = swap ? g_hA : g_hB;
    const float* hT_r = swap ? g_hTB : g_hTA;
    float*       hT_w = swap ? g_hTA : g_hTB;

    const int pl = tid & 127, ch2 = tid >> 7;
    const int p = p0 + pl;
    const int py = p / Ww, px = p - py * Ww;
    const float* Fb = g_flows + (size_t)b * 2 * Lq * HW;
    const float* hTbase = hT_r + (size_t)b * HW * HID;

    float acc[4][6][4];
#pragma unroll
    for (int mt = 0; mt < 4; mt++)
#pragma unroll
        for (int nt = 0; nt < 6; nt++)
#pragma unroll
            for (int q = 0; q < 4; q++) acc[mt][nt][q] = 0.f;

    float w00 = 0, w01 = 0, w10 = 0, w11 = 0;
    int o00 = 0, o01 = 0, o10 = 0, o11 = 0;

#define BILIN_PARAMS(L) do {                                                  \
        float fx = Fb[(size_t)(2 * (L)) * HW + p];                            \
        float fy = Fb[(size_t)(2 * (L) + 1) * HW + p];                        \
        float ix = (float)px - fx - 0.5f;                                     \
        float iy = (float)py - fy - 0.5f;                                     \
        float ix0f = floorf(ix), iy0f = floorf(iy);                           \
        float wx1 = ix - ix0f, wy1 = iy - iy0f;                               \
        float wx0 = 1.f - wx1, wy0 = 1.f - wy1;                               \
        int ix0 = (int)ix0f, iy0 = (int)iy0f;                                 \
        int ix1 = ix0 + 1, iy1 = iy0 + 1;                                     \
        bool vx0 = (ix0 >= 0 && ix0 < Ww), vx1 = (ix1 >= 0 && ix1 < Ww);      \
        bool vy0 = (iy0 >= 0 && iy0 < Hh), vy1 = (iy1 >= 0 && iy1 < Hh);      \
        w00 = (vy0 && vx0) ? wy0 * wx0 : 0.f;                                 \
        w01 = (vy0 && vx1) ? wy0 * wx1 : 0.f;                                 \
        w10 = (vy1 && vx0) ? wy1 * wx0 : 0.f;                                 \
        w11 = (vy1 && vx1) ? wy1 * wx1 : 0.f;                                 \
        int xc0 = min(max(ix0, 0), Ww - 1), xc1 = min(max(ix1, 0), Ww - 1);   \
        int yc0 = min(max(iy0, 0), Hh - 1), yc1 = min(max(iy1, 0), Hh - 1);   \
        o00 = yc0 * Ww + xc0; o01 = yc0 * Ww + xc1;                           \
        o10 = yc1 * Ww + xc0; o11 = yc1 * Ww + xc1;                           \
    } while (0)

// gather 16 channels via float4 loads from channel-contiguous hT
#define GATHER16(vals, CH0) do {                                              \
        const float* c00_ = hTbase + (size_t)o00 * HID + (CH0);               \
        const float* c01_ = hTbase + (size_t)o01 * HID + (CH0);               \
        const float* c10_ = hTbase + (size_t)o10 * HID + (CH0);               \
        const float* c11_ = hTbase + (size_t)o11 * HID + (CH0);               \
        _Pragma("unroll")                                                     \
        for (int jj = 0; jj < 4; jj++) {                                      \
            float4 v00 = *(const float4*)(c00_ + 4 * jj);                     \
            float4 v01 = *(const float4*)(c01_ + 4 * jj);                     \
            float4 v10 = *(const float4*)(c10_ + 4 * jj);                     \
            float4 v11 = *(const float4*)(c11_ + 4 * jj);                     \
            (vals)[4 * jj + 0] = w00 * v00.x + w01 * v01.x + w10 * v10.x + w11 * v11.x; \
            (vals)[4 * jj + 1] = w00 * v00.y + w01 * v01.y + w10 * v10.y + w11 * v11.y; \
            (vals)[4 * jj + 2] = w00 * v00.z + w01 * v01.z + w10 * v10.z + w11 * v11.z; \
            (vals)[4 * jj + 3] = w00 * v00.w + w01 * v01.w + w10 * v10.w + w11 * v11.w; \
        }                                                                     \
    } while (0)

#define STAGE_A(S, VALS) do {                                                 \
        uint32_t* Adst = (uint32_t*)sm + (S) * A_ST_W + pl * AW + ch2 * 8;    \
        uint32_t hw_[8];                                                      \
        _Pragma("unroll")                                                     \
        for (int jj = 0; jj < 8; jj++) {                                      \
            asm("cvt.rn.satfinite.bf16x2.f32 %0, %1, %2;"                     \
                : "=r"(hw_[jj]) : "f"((VALS)[2 * jj + 1]), "f"((VALS)[2 * jj])); \
        }                                                                     \
        *(uint4*)(Adst)     = make_uint4(hw_[0], hw_[1], hw_[2], hw_[3]);     \
        *(uint4*)(Adst + 4) = make_uint4(hw_[4], hw_[5], hw_[6], hw_[7]);     \
    } while (0)

#define STAGE_B(S, K0) do {                                                   \
        uint32_t sb_ = sm_sh + (uint32_t)(B_OFF_W + (S) * B_ST_W) * 4;        \
        _Pragma("unroll")                                                     \
        for (int i_ = 0; i_ < 6; i_++) {                                      \
            int idx_ = tid + 256 * i_;                                        \
            const __nv_bfloat16* src_ = g_Bh16;                               \
            uint32_t dst_ = sb_;                                              \
            int j_ = idx_;                                                    \
            if (idx_ >= 768) { j_ -= 768; src_ = g_Bl16; dst_ += B_LO_W * 4; }\
            int row_ = j_ >> 2, cc_ = j_ & 3;                                 \
            CP_ASYNC16(dst_ + row_ * 80 + cc_ * 16,                           \
                       src_ + (size_t)row_ * KW + (K0) + cc_ * 8);            \
        }                                                                     \
        CP_COMMIT();                                                          \
    } while (0)

    // ---- preamble ----
    float vals[16];
    BILIN_PARAMS(0);
    GATHER16(vals, ch2 * 16);
    STAGE_A(0, vals);
    STAGE_B(0, 0);
    GATHER16(vals, 32 + ch2 * 16);

    for (int c = 0; c < 26; c++) {
        const int s = c & 1;
        CP_WAIT0();
        __syncthreads();

        if (c < 25) {
            STAGE_A(s ^ 1, vals);
            STAGE_B(s ^ 1, (c + 1) * 32);
        }
        if (c < 24) {
            if (((c + 2) & 1) == 0) BILIN_PARAMS((c + 2) >> 1);
            GATHER16(vals, (((c + 2) * 32) & 32) + ch2 * 16);
        }

        // ---- MMA on stage s ----
        const uint32_t* Ah = (const uint32_t*)sm + s * A_ST_W;
        const uint32_t* Bh = (const uint32_t*)sm + B_OFF_W + s * B_ST_W;
        const uint32_t* Bl = Bh + B_LO_W;
#pragma unroll
        for (int ks = 0; ks < 2; ks++) {
            uint32_t ahi[4][4];
#pragma unroll
            for (int mt = 0; mt < 4; mt++) {
                int base = (wm + mt * 16 + g) * AW + ks * 8 + tg;
                ahi[mt][0] = Ah[base];            ahi[mt][2] = Ah[base + 4];
                ahi[mt][1] = Ah[base + 8 * AW];   ahi[mt][3] = Ah[base + 8 * AW + 4];
            }
#pragma unroll
            for (int nt = 0; nt < 6; nt++) {
                int col = wn16 + (nt >> 1) * 64 + (nt & 1) * 8;
                int rb = (col + g) * AW + ks * 8 + tg;
                uint32_t bh0 = Bh[rb], bh1 = Bh[rb + 4];
                uint32_t bl0 = Bl[rb], bl1 = Bl[rb + 4];
#pragma unroll
                for (int mt = 0; mt < 4; mt++) {
                    mma16(acc[mt][nt], ahi[mt], bh0, bh1);
                    mma16(acc[mt][nt], ahi[mt], bl0, bl1);
                }
            }
        }
    }

    // ---- register gate epilogue ----
    const float* i2hp = g_i2h + (size_t)(b * Tt + t) * C3 * HW;
#pragma unroll
    for (int mt = 0; mt < 4; mt++) {
        int prow = p0 + wm + mt * 16 + g;
#pragma unroll
        for (int ntr = 0; ntr < 2; ntr++) {
            int cc0 = wn16 + ntr * 8 + tg * 2;
#pragma unroll
            for (int q = 0; q < 4; q++) {
                int pp = prow + (q >> 1) * 8;
                int cc = cc0 + (q & 1);
                float rh = acc[mt][ntr][q]     + __ldg(&wrap_b[cc]);
                float uh = acc[mt][ntr + 2][q] + __ldg(&wrap_b[cc + 64]);
                float nh = acc[mt][ntr + 4][q] + __ldg(&wrap_b[cc + 128]);
                float r = sigmoid_fast(i2hp[(size_t)cc * HW + pp] + rh);
                float u = sigmoid_fast(i2hp[(size_t)(cc + 64) * HW + pp] + uh);
                float n = sigmoid_fast(i2hp[(size_t)(cc + 128) * HW + pp] + r * nh);
                size_t hidx = ((size_t)b * HID + cc) * HW + pp;
                float hp = h_r[hidx];
                float hn = (1.f - u) * n + u * hp;
                h_w[hidx] = hn;
                hT_w[((size_t)b * HW + pp) * HID + cc] = hn;
                out[((size_t)(b * Tt + t) * HID + cc) * HW + pp] = hn;
            }
        }
    }
}

// ---------------------------------------------------------------------------
extern "C" void kernel_launch(void* const* d_in, const int* in_sizes, int n_in,
                              void* d_out, int out_size) {
    const float* inputs  = (const float*)d_in[0];
    const float* state   = (const float*)d_in[1];
    const float* i2h_w   = (const float*)d_in[2];
    const float* i2h_b   = (const float*)d_in[3];
    const float* i2f_w   = (const float*)d_in[4];
    const float* i2f_b   = (const float*)d_in[5];
    const float* h2f_w   = (const float*)d_in[6];
    const float* h2f_b   = (const float*)d_in[7];
    const float* flows_w = (const float*)d_in[8];
    const float* flows_b = (const float*)d_in[9];
    const float* wrap_w  = (const float*)d_in[10];
    const float* wrap_b  = (const float*)d_in[11];
    float* out = (float*)d_out;

    cudaFuncSetAttribute(k_gemm_mma, cudaFuncAttributeMaxDynamicSharedMemorySize,
                         G_SMEM_BYTES);

    const int nh = Bq * HID * HW;
    k_init_h<<<(nh + 255) / 256, 256>>>(state);
    k_prep_b<<<(C3 * KW + 255) / 256, 256>>>(wrap_w);
    k_i2h<<<dim3(6, 6, 240), 128>>>(inputs, i2h_w, i2h_b);

    for (int t = 0; t < Tt; t++) {
        int swap = t & 1;
        k_fconv_half<<<dim3(6, 6, 16), 128>>>(inputs, t, swap,
                                              i2f_w, i2f_b, h2f_w, h2f_b);
        k_flows<<<dim3(6, 6, 8), 128>>>(flows_w, flows_b);
        k_gemm_mma<<<dim3(HW / 128, Bq), 256, G_SMEM_BYTES>>>(wrap_b, out, t, swap);
    }

    long long outputs_elems = (long long)Bq * Tt * HID * HW;
    if ((long long)out_size >= outputs_elems + nh) {
        k_hlast<<<(nh + 255) / 256, 256>>>(out + outputs_elems);
    }
}

// round 16
// speedup vs baseline: 1.2234x; 1.2234x over previous
#include <cuda_runtime.h>
#include <cuda_bf16.h>
#include <math.h>
#include <stdint.h>

// ---- problem constants ----
#define Bq   4
#define Tt   10
#define CINq 8
#define Hh   96
#define Ww   96
#define HW   9216
#define HID  64
#define Lq   13
#define C3   192
#define KW   832
#define FCH  32

// ---- scratch ----
__device__ float g_i2h[(size_t)Bq * Tt * C3 * HW];
__device__ float g_hA[(size_t)Bq * HID * HW];
__device__ float g_hB[(size_t)Bq * HID * HW];
__device__ float g_fp0[(size_t)Bq * FCH * HW];      // fconv partials
__device__ float g_fp1[(size_t)Bq * FCH * HW];
__device__ float g_fl0[(size_t)Bq * 2 * Lq * HW];   // flows partials
__device__ float g_fl1[(size_t)Bq * 2 * Lq * HW];
__device__ __nv_bfloat16 g_Bh16[(size_t)C3 * KW];
__device__ __nv_bfloat16 g_Bl16[(size_t)C3 * KW];

// ---- helpers ----
typedef unsigned long long u64;
__device__ __forceinline__ u64 pack2(float x, float y) {
    u64 r; asm("mov.b64 %0, {%1,%2};" : "=l"(r) : "f"(x), "f"(y)); return r;
}
__device__ __forceinline__ void unpack2(u64 v, float& x, float& y) {
    asm("mov.b64 {%0,%1}, %2;" : "=f"(x), "=f"(y) : "l"(v));
}
__device__ __forceinline__ void fma2(u64& d, u64 a, u64 b) {
    asm("fma.rn.f32x2 %0, %1, %2, %0;" : "+l"(d) : "l"(a), "l"(b));
}
__device__ __forceinline__ float tanh_fast(float x) {
    float t = __expf(-2.f * fabsf(x));
    float r = (1.f - t) / (1.f + t);
    return copysignf(r, x);
}
__device__ __forceinline__ float sigmoid_fast(float x) {
    return 1.f / (1.f + __expf(-x));
}
#define CP_ASYNC16(dst, src) \
    asm volatile("cp.async.cg.shared.global [%0], [%1], 16;" :: "r"(dst), "l"(src))
#define CP_COMMIT() asm volatile("cp.async.commit_group;")
#define CP_WAIT0()  asm volatile("cp.async.wait_group 0;")

// ---------------------------------------------------------------------------
__global__ void k_init_h(const float* __restrict__ state) {
    int i = blockIdx.x * 256 + threadIdx.x;
    if (i < Bq * HID * HW) g_hA[i] = state[i];
}
__global__ void k_hlast(float* __restrict__ dst) {
    int i = blockIdx.x * 256 + threadIdx.x;
    if (i < Bq * HID * HW) dst[i] = g_hA[i];
}
__global__ void k_prep_b(const float* __restrict__ wrap_w) {
    int i = blockIdx.x * 256 + threadIdx.x;
    if (i < C3 * KW) {
        float v = wrap_w[i];
        __nv_bfloat16 h = __float2bfloat16(v);
        g_Bh16[i] = h;
        g_Bl16[i] = __float2bfloat16(v - __bfloat162float(h));
    }
}

// ---------------------------------------------------------------------------
// i2h: conv3x3 pad1. grid (6,6,240): z = n + 40*cog, cog selects 32 co.
__global__ __launch_bounds__(128)
void k_i2h(const float* __restrict__ x, const float* __restrict__ w,
           const float* __restrict__ bias) {
    __shared__ float s_in[CINq * 18 * 18];
    __shared__ __align__(16) float s_w[72 * 32];
    const int n   = blockIdx.z % 40;
    const int cob = (blockIdx.z / 40) * 32;
    const int y0 = blockIdx.y * 16, x0 = blockIdx.x * 16;
    const int tid = threadIdx.x;
    const int tx = tid & 15, ty = tid >> 4;

    const float* xin = x + (size_t)n * CINq * HW;
    for (int idx = tid; idx < CINq * 18 * 18; idx += 128) {
        int ci = idx / 324, r = (idx / 18) % 18, c = idx % 18;
        int gy = y0 - 1 + r, gx = x0 - 1 + c;
        float v = 0.f;
        if (gy >= 0 && gy < Hh && gx >= 0 && gx < Ww) v = xin[ci * HW + gy * Ww + gx];
        s_in[idx] = v;
    }
    for (int idx = tid; idx < 72 * 32; idx += 128) {
        int kk = idx >> 5, co = idx & 31;
        s_w[idx] = w[(cob + co) * 72 + kk];
    }
    __syncthreads();

    u64 accA[16], accB[16];
#pragma unroll
    for (int q = 0; q < 16; q++) {
        u64 v = pack2(bias[cob + 2 * q], bias[cob + 2 * q + 1]);
        accA[q] = v; accB[q] = v;
    }
    const u64* sw8 = (const u64*)s_w;
    for (int ci = 0; ci < CINq; ci++) {
#pragma unroll
        for (int ky = 0; ky < 3; ky++) {
            const float* r0 = &s_in[ci * 324 + (ty + ky) * 18 + tx];
            const float* r1 = &s_in[ci * 324 + (ty + 8 + ky) * 18 + tx];
#pragma unroll
            for (int kx = 0; kx < 3; kx++) {
                u64 a0 = pack2(r0[kx], r0[kx]);
                u64 a1 = pack2(r1[kx], r1[kx]);
                const u64* wp = sw8 + (ci * 9 + ky * 3 + kx) * 16;
#pragma unroll
                for (int h = 0; h < 4; h++) {
                    ulonglong2 wA = *(const ulonglong2*)(wp + h * 4);
                    ulonglong2 wB = *(const ulonglong2*)(wp + h * 4 + 2);
                    fma2(accA[h * 4 + 0], a0, wA.x); fma2(accB[h * 4 + 0], a1, wA.x);
                    fma2(accA[h * 4 + 1], a0, wA.y); fma2(accB[h * 4 + 1], a1, wA.y);
                    fma2(accA[h * 4 + 2], a0, wB.x); fma2(accB[h * 4 + 2], a1, wB.x);
                    fma2(accA[h * 4 + 3], a0, wB.y); fma2(accB[h * 4 + 3], a1, wB.y);
                }
            }
        }
    }
    float* outp = g_i2h + (size_t)n * C3 * HW + (size_t)cob * HW + (y0 + ty) * Ww + (x0 + tx);
#pragma unroll
    for (int q = 0; q < 16; q++) {
        float v0, v1, v2, v3;
        unpack2(accA[q], v0, v1);
        unpack2(accB[q], v2, v3);
        outp[(size_t)(2 * q) * HW] = v0;
        outp[(size_t)(2 * q + 1) * HW] = v1;
        outp[(size_t)(2 * q) * HW + 8 * Ww] = v2;
        outp[(size_t)(2 * q + 1) * HW + 8 * Ww] = v3;
    }
}

// ---------------------------------------------------------------------------
// fconv split by input chunks. grid (6,6,16): z = b + 4*grp + 8*half.
__global__ __launch_bounds__(128)
void k_fconv_half(const float* __restrict__ xall, int t, int swap,
                  const float* __restrict__ wi, const float* __restrict__ bi,
                  const float* __restrict__ wh, const float* __restrict__ bh) {
    __shared__ float s_in[8 * 400];
    __shared__ __align__(16) float s_w[200 * 16];
    const int b    = blockIdx.z & 3;
    const int grp  = (blockIdx.z >> 2) & 1;
    const int half = blockIdx.z >> 3;
    const int co0 = grp * 16;
    const int y0 = blockIdx.y * 16, x0 = blockIdx.x * 16;
    const int tid = threadIdx.x;
    const int tx = tid & 15, ty = tid >> 4;
    const float* hsrc = swap ? g_hB : g_hA;

    u64 accA[8], accB[8];
#pragma unroll
    for (int q = 0; q < 8; q++) {
        u64 v = half ? 0ull
                     : pack2(bi[co0 + 2 * q] + bh[co0 + 2 * q],
                             bi[co0 + 2 * q + 1] + bh[co0 + 2 * q + 1]);
        accA[q] = v; accB[q] = v;
    }

    const int c_lo = half ? 5 : 0;
    const int c_hi = half ? 9 : 5;
    for (int chunk = c_lo; chunk < c_hi; chunk++) {
        const float* src = (chunk == 0)
            ? xall + (size_t)(b * Tt + t) * CINq * HW
            : hsrc + (size_t)b * HID * HW + (size_t)(chunk - 1) * 8 * HW;
        __syncthreads();
        for (int idx = tid; idx < 8 * 400; idx += 128) {
            int ci = idx / 400, r = (idx / 20) % 20, c = idx % 20;
            int gy = y0 - 2 + r, gx = x0 - 2 + c;
            float v = 0.f;
            if (gy >= 0 && gy < Hh && gx >= 0 && gx < Ww) v = src[ci * HW + gy * Ww + gx];
            s_in[idx] = v;
        }
        if (chunk == 0) {
            for (int idx = tid; idx < 200 * 16; idx += 128) {
                int kk = idx >> 4, co = idx & 15;
                s_w[idx] = wi[(co0 + co) * 200 + kk];
            }
        } else {
            int cioff = (chunk - 1) * 8;
            for (int idx = tid; idx < 200 * 16; idx += 128) {
                int kk = idx >> 4, co = idx & 15;
                int ci = kk / 25, k25 = kk % 25;
                s_w[idx] = wh[((co0 + co) * 64 + cioff + ci) * 25 + k25];
            }
        }
        __syncthreads();
        const u64* sw8 = (const u64*)s_w;
        for (int ci = 0; ci < 8; ci++) {
#pragma unroll
            for (int ky = 0; ky < 5; ky++) {
                const float* r0 = &s_in[ci * 400 + (ty + ky) * 20 + tx];
                const float* r1 = &s_in[ci * 400 + (ty + 8 + ky) * 20 + tx];
#pragma unroll
                for (int kx = 0; kx < 5; kx++) {
                    u64 a0 = pack2(r0[kx], r0[kx]);
                    u64 a1 = pack2(r1[kx], r1[kx]);
                    const u64* wp = sw8 + (ci * 25 + ky * 5 + kx) * 8;
#pragma unroll
                    for (int h = 0; h < 2; h++) {
                        ulonglong2 wA = *(const ulonglong2*)(wp + h * 4);
                        ulonglong2 wB = *(const ulonglong2*)(wp + h * 4 + 2);
                        fma2(accA[h * 4 + 0], a0, wA.x); fma2(accB[h * 4 + 0], a1, wA.x);
                        fma2(accA[h * 4 + 1], a0, wA.y); fma2(accB[h * 4 + 1], a1, wA.y);
                        fma2(accA[h * 4 + 2], a0, wB.x); fma2(accB[h * 4 + 2], a1, wB.x);
                        fma2(accA[h * 4 + 3], a0, wB.y); fma2(accB[h * 4 + 3], a1, wB.y);
                    }
                }
            }
        }
    }
    float* base = half ? g_fp1 : g_fp0;
    float* outp = base + (size_t)b * FCH * HW + (size_t)co0 * HW + (y0 + ty) * Ww + (x0 + tx);
#pragma unroll
    for (int q = 0; q < 8; q++) {
        float v0, v1, v2, v3;
        unpack2(accA[q], v0, v1);
        unpack2(accB[q], v2, v3);
        outp[(size_t)(2 * q) * HW] = v0;
        outp[(size_t)(2 * q + 1) * HW] = v1;
        outp[(size_t)(2 * q) * HW + 8 * Ww] = v2;
        outp[(size_t)(2 * q + 1) * HW + 8 * Ww] = v3;
    }
}

// ---------------------------------------------------------------------------
// flows = conv5x5(tanh(fp0+fp1)), split by input chunks into 2 halves.
// grid (6,6,16): z = b + 4*grp + 8*half. half0: chunks 0-1 + bias; half1: 2-3.
// Partials to g_fl0/g_fl1 (combined in GEMM's flow read).
__global__ __launch_bounds__(128)
void k_flows_half(const float* __restrict__ w, const float* __restrict__ bias) {
    __shared__ float s_in[8 * 400];
    __shared__ __align__(16) float s_w[200 * 14];
    const int b    = blockIdx.z & 3;
    const int grp  = (blockIdx.z >> 2) & 1;
    const int half = blockIdx.z >> 3;
    const int co0 = grp * 13;
    const int y0 = blockIdx.y * 16, x0 = blockIdx.x * 16;
    const int tid = threadIdx.x;
    const int tx = tid & 15, ty = tid >> 4;

    u64 accA[7], accB[7];
#pragma unroll
    for (int q = 0; q < 7; q++) {
        u64 v = 0ull;
        if (!half) {
            float b0 = bias[co0 + 2 * q];
            float b1 = (2 * q + 1 < 13) ? bias[co0 + 2 * q + 1] : 0.f;
            v = pack2(b0, b1);
        }
        accA[q] = v; accB[q] = v;
    }

    const int c_lo = half ? 2 : 0;
    const int c_hi = half ? 4 : 2;
    for (int chunk = c_lo; chunk < c_hi; chunk++) {
        const float* s0 = g_fp0 + (size_t)b * FCH * HW + (size_t)chunk * 8 * HW;
        const float* s1 = g_fp1 + (size_t)b * FCH * HW + (size_t)chunk * 8 * HW;
        __syncthreads();
        for (int idx = tid; idx < 8 * 400; idx += 128) {
            int ci = idx / 400, r = (idx / 20) % 20, c = idx % 20;
            int gy = y0 - 2 + r, gx = x0 - 2 + c;
            float v = 0.f;
            if (gy >= 0 && gy < Hh && gx >= 0 && gx < Ww) {
                int off = ci * HW + gy * Ww + gx;
                v = tanh_fast(s0[off] + s1[off]);
            }
            s_in[idx] = v;
        }
        int cioff = chunk * 8;
        for (int idx = tid; idx < 200 * 14; idx += 128) {
            int kk = idx / 14, co = idx % 14;
            int ci = kk / 25, k25 = kk % 25;
            float v = 0.f;
            if (co < 13) v = w[((co0 + co) * 32 + cioff + ci) * 25 + k25];
            s_w[idx] = v;
        }
        __syncthreads();
        const u64* sw8 = (const u64*)s_w;
        for (int ci = 0; ci < 8; ci++) {
#pragma unroll
            for (int ky = 0; ky < 5; ky++) {
                const float* r0 = &s_in[ci * 400 + (ty + ky) * 20 + tx];
                const float* r1 = &s_in[ci * 400 + (ty + 8 + ky) * 20 + tx];
#pragma unroll
                for (int kx = 0; kx < 5; kx++) {
                    u64 a0 = pack2(r0[kx], r0[kx]);
                    u64 a1 = pack2(r1[kx], r1[kx]);
                    const u64* wp = sw8 + (ci * 25 + ky * 5 + kx) * 7;
#pragma unroll
                    for (int q = 0; q < 7; q++) {
                        u64 w2 = wp[q];
                        fma2(accA[q], a0, w2);
                        fma2(accB[q], a1, w2);
                    }
                }
            }
        }
    }
    float* base = half ? g_fl1 : g_fl0;
    float* outp = base + (size_t)b * 2 * Lq * HW + (size_t)co0 * HW + (y0 + ty) * Ww + (x0 + tx);
#pragma unroll
    for (int q = 0; q < 7; q++) {
        float v0, v1, v2, v3;
        unpack2(accA[q], v0, v1);
        unpack2(accB[q], v2, v3);
        outp[(size_t)(2 * q) * HW] = v0;
        outp[(size_t)(2 * q) * HW + 8 * Ww] = v2;
        if (2 * q + 1 < 13) {
            outp[(size_t)(2 * q + 1) * HW] = v1;
            outp[(size_t)(2 * q + 1) * HW + 8 * Ww] = v3;
        }
    }
}

// ---------------------------------------------------------------------------
// h2h GEMM: bf16 m16n8k16, 2-term. Double-buffered, fused planar gather
// (flow = fl0+fl1) + register gate epilogue.  [R14 GEMM + partial-flow sum]
#define AW 20
#define A_ST_W 2560
#define B_OFF_W 5120
#define B_ST_W 7680
#define B_LO_W 3840
#define G_SMEM_BYTES 81920

__device__ __forceinline__ void mma16(float d[4], const uint32_t a[4],
                                      uint32_t b0, uint32_t b1) {
    asm volatile(
        "mma.sync.aligned.m16n8k16.row.col.f32.bf16.bf16.f32 "
        "{%0,%1,%2,%3}, {%4,%5,%6,%7}, {%8,%9}, {%0,%1,%2,%3};"
        : "+f"(d[0]), "+f"(d[1]), "+f"(d[2]), "+f"(d[3])
        : "r"(a[0]), "r"(a[1]), "r"(a[2]), "r"(a[3]), "r"(b0), "r"(b1));
}

__global__ __launch_bounds__(256, 1)
void k_gemm_mma(const float* __restrict__ wrap_b, float* __restrict__ out,
                int t, int swap) {
    extern __shared__ __align__(16) float sm[];
    const uint32_t sm_sh = (uint32_t)__cvta_generic_to_shared(sm);

    const int tid = threadIdx.x;
    const int wid = tid >> 5, lane = tid & 31;
    const int g = lane >> 2, tg = lane & 3;
    const int b  = blockIdx.y;
    const int p0 = blockIdx.x * 128;
    const int wm = (wid >> 2) * 64;
    const int wn16 = (wid & 3) * 16;

    const float* h_r = swap ? g_hB : g_hA;
    float*       h_w = swap ? g_hA : g_hB;

    const int pl = tid & 127, ch2 = tid >> 7;
    const int p = p0 + pl;
    const int py = p / Ww, px = p - py * Ww;
    const float* Fb0 = g_fl0 + (size_t)b * 2 * Lq * HW;
    const float* Fb1 = g_fl1 + (size_t)b * 2 * Lq * HW;
    const float* hbase = h_r + (size_t)b * HID * HW;

    float acc[4][6][4];
#pragma unroll
    for (int mt = 0; mt < 4; mt++)
#pragma unroll
        for (int nt = 0; nt < 6; nt++)
#pragma unroll
            for (int q = 0; q < 4; q++) acc[mt][nt][q] = 0.f;

    float w00 = 0, w01 = 0, w10 = 0, w11 = 0;
    int o00 = 0, o01 = 0, o10 = 0, o11 = 0;

#define BILIN_PARAMS(L) do {                                                  \
        size_t ofx = (size_t)(2 * (L)) * HW + p;                              \
        size_t ofy = (size_t)(2 * (L) + 1) * HW + p;                          \
        float fx = Fb0[ofx] + Fb1[ofx];                                       \
        float fy = Fb0[ofy] + Fb1[ofy];                                       \
        float ix = (float)px - fx - 0.5f;                                     \
        float iy = (float)py - fy - 0.5f;                                     \
        float ix0f = floorf(ix), iy0f = floorf(iy);                           \
        float wx1 = ix - ix0f, wy1 = iy - iy0f;                               \
        float wx0 = 1.f - wx1, wy0 = 1.f - wy1;                               \
        int ix0 = (int)ix0f, iy0 = (int)iy0f;                                 \
        int ix1 = ix0 + 1, iy1 = iy0 + 1;                                     \
        bool vx0 = (ix0 >= 0 && ix0 < Ww), vx1 = (ix1 >= 0 && ix1 < Ww);      \
        bool vy0 = (iy0 >= 0 && iy0 < Hh), vy1 = (iy1 >= 0 && iy1 < Hh);      \
        w00 = (vy0 && vx0) ? wy0 * wx0 : 0.f;                                 \
        w01 = (vy0 && vx1) ? wy0 * wx1 : 0.f;                                 \
        w10 = (vy1 && vx0) ? wy1 * wx0 : 0.f;                                 \
        w11 = (vy1 && vx1) ? wy1 * wx1 : 0.f;                                 \
        int xc0 = min(max(ix0, 0), Ww - 1), xc1 = min(max(ix1, 0), Ww - 1);   \
        int yc0 = min(max(iy0, 0), Hh - 1), yc1 = min(max(iy1, 0), Hh - 1);   \
        o00 = yc0 * Ww + xc0; o01 = yc0 * Ww + xc1;                           \
        o10 = yc1 * Ww + xc0; o11 = yc1 * Ww + xc1;                           \
    } while (0)

#define GATHER16(vals, CH0) do {                                              \
        const float* hb_ = hbase + (size_t)(CH0) * HW;                        \
        _Pragma("unroll")                                                     \
        for (int q_ = 0; q_ < 16; q_++) {                                     \
            const float* hc_ = hb_ + (size_t)q_ * HW;                         \
            (vals)[q_] = w00 * hc_[o00] + w01 * hc_[o01]                      \
                       + w10 * hc_[o10] + w11 * hc_[o11];                     \
        }                                                                     \
    } while (0)

#define STAGE_A(S, VALS) do {                                                 \
        uint32_t* Adst = (uint32_t*)sm + (S) * A_ST_W + pl * AW + ch2 * 8;    \
        uint32_t hw_[8];                                                      \
        _Pragma("unroll")                                                     \
        for (int jj = 0; jj < 8; jj++) {                                      \
            asm("cvt.rn.satfinite.bf16x2.f32 %0, %1, %2;"                     \
                : "=r"(hw_[jj]) : "f"((VALS)[2 * jj + 1]), "f"((VALS)[2 * jj])); \
        }                                                                     \
        *(uint4*)(Adst)     = make_uint4(hw_[0], hw_[1], hw_[2], hw_[3]);     \
        *(uint4*)(Adst + 4) = make_uint4(hw_[4], hw_[5], hw_[6], hw_[7]);     \
    } while (0)

#define STAGE_B(S, K0) do {                                                   \
        uint32_t sb_ = sm_sh + (uint32_t)(B_OFF_W + (S) * B_ST_W) * 4;        \
        _Pragma("unroll")                                                     \
        for (int i_ = 0; i_ < 6; i_++) {                                      \
            int idx_ = tid + 256 * i_;                                        \
            const __nv_bfloat16* src_ = g_Bh16;                               \
            uint32_t dst_ = sb_;                                              \
            int j_ = idx_;                                                    \
            if (idx_ >= 768) { j_ -= 768; src_ = g_Bl16; dst_ += B_LO_W * 4; }\
            int row_ = j_ >> 2, cc_ = j_ & 3;                                 \
            CP_ASYNC16(dst_ + row_ * 80 + cc_ * 16,                           \
                       src_ + (size_t)row_ * KW + (K0) + cc_ * 8);            \
        }                                                                     \
        CP_COMMIT();                                                          \
    } while (0)

    // ---- preamble ----
    float vals[16];
    BILIN_PARAMS(0);
    GATHER16(vals, ch2 * 16);
    STAGE_A(0, vals);
    STAGE_B(0, 0);
    GATHER16(vals, 32 + ch2 * 16);

    for (int c = 0; c < 26; c++) {
        const int s = c & 1;
        CP_WAIT0();
        __syncthreads();

        if (c < 25) {
            STAGE_A(s ^ 1, vals);
            STAGE_B(s ^ 1, (c + 1) * 32);
        }
        if (c < 24) {
            if (((c + 2) & 1) == 0) BILIN_PARAMS((c + 2) >> 1);
            GATHER16(vals, (((c + 2) * 32) & 32) + ch2 * 16);
        }

        // ---- MMA on stage s ----
        const uint32_t* Ah = (const uint32_t*)sm + s * A_ST_W;
        const uint32_t* Bh = (const uint32_t*)sm + B_OFF_W + s * B_ST_W;
        const uint32_t* Bl = Bh + B_LO_W;
#pragma unroll
        for (int ks = 0; ks < 2; ks++) {
            uint32_t ahi[4][4];
#pragma unroll
            for (int mt = 0; mt < 4; mt++) {
                int base = (wm + mt * 16 + g) * AW + ks * 8 + tg;
                ahi[mt][0] = Ah[base];            ahi[mt][2] = Ah[base + 4];
                ahi[mt][1] = Ah[base + 8 * AW];   ahi[mt][3] = Ah[base + 8 * AW + 4];
            }
#pragma unroll
            for (int nt = 0; nt < 6; nt++) {
                int col = wn16 + (nt >> 1) * 64 + (nt & 1) * 8;
                int rb = (col + g) * AW + ks * 8 + tg;
                uint32_t bh0 = Bh[rb], bh1 = Bh[rb + 4];
                uint32_t bl0 = Bl[rb], bl1 = Bl[rb + 4];
#pragma unroll
                for (int mt = 0; mt < 4; mt++) {
                    mma16(acc[mt][nt], ahi[mt], bh0, bh1);
                    mma16(acc[mt][nt], ahi[mt], bl0, bl1);
                }
            }
        }
    }

    // ---- register gate epilogue ----
    const float* i2hp = g_i2h + (size_t)(b * Tt + t) * C3 * HW;
#pragma unroll
    for (int mt = 0; mt < 4; mt++) {
        int prow = p0 + wm + mt * 16 + g;
#pragma unroll
        for (int ntr = 0; ntr < 2; ntr++) {
            int cc0 = wn16 + ntr * 8 + tg * 2;
#pragma unroll
            for (int q = 0; q < 4; q++) {
                int pp = prow + (q >> 1) * 8;
                int cc = cc0 + (q & 1);
                float rh = acc[mt][ntr][q]     + __ldg(&wrap_b[cc]);
                float uh = acc[mt][ntr + 2][q] + __ldg(&wrap_b[cc + 64]);
                float nh = acc[mt][ntr + 4][q] + __ldg(&wrap_b[cc + 128]);
                float r = sigmoid_fast(i2hp[(size_t)cc * HW + pp] + rh);
                float u = sigmoid_fast(i2hp[(size_t)(cc + 64) * HW + pp] + uh);
                float n = sigmoid_fast(i2hp[(size_t)(cc + 128) * HW + pp] + r * nh);
                size_t hidx = ((size_t)b * HID + cc) * HW + pp;
                float hp = h_r[hidx];
                float hn = (1.f - u) * n + u * hp;
                h_w[hidx] = hn;
                out[((size_t)(b * Tt + t) * HID + cc) * HW + pp] = hn;
            }
        }
    }
}

// ---------------------------------------------------------------------------
extern "C" void kernel_launch(void* const* d_in, const int* in_sizes, int n_in,
                              void* d_out, int out_size) {
    const float* inputs  = (const float*)d_in[0];
    const float* state   = (const float*)d_in[1];
    const float* i2h_w   = (const float*)d_in[2];
    const float* i2h_b   = (const float*)d_in[3];
    const float* i2f_w   = (const float*)d_in[4];
    const float* i2f_b   = (const float*)d_in[5];
    const float* h2f_w   = (const float*)d_in[6];
    const float* h2f_b   = (const float*)d_in[7];
    const float* flows_w = (const float*)d_in[8];
    const float* flows_b = (const float*)d_in[9];
    const float* wrap_w  = (const float*)d_in[10];
    const float* wrap_b  = (const float*)d_in[11];
    float* out = (float*)d_out;

    cudaFuncSetAttribute(k_gemm_mma, cudaFuncAttributeMaxDynamicSharedMemorySize,
                         G_SMEM_BYTES);

    const int nh = Bq * HID * HW;
    k_init_h<<<(nh + 255) / 256, 256>>>(state);
    k_prep_b<<<(C3 * KW + 255) / 256, 256>>>(wrap_w);
    k_i2h<<<dim3(6, 6, 240), 128>>>(inputs, i2h_w, i2h_b);

    for (int t = 0; t < Tt; t++) {
        int swap = t & 1;
        k_fconv_half<<<dim3(6, 6, 16), 128>>>(inputs, t, swap,
                                              i2f_w, i2f_b, h2f_w, h2f_b);
        k_flows_half<<<dim3(6, 6, 16), 128>>>(flows_w, flows_b);
        k_gemm_mma<<<dim3(HW / 128, Bq), 256, G_SMEM_BYTES>>>(wrap_b, out, t, swap);
    }

    long long outputs_elems = (long long)Bq * Tt * HID * HW;
    if ((long long)out_size >= outputs_elems + nh) {
        k_hlast<<<(nh + 255) / 256, 256>>>(out + outputs_elems);
    }
}